// round 4
// baseline (speedup 1.0000x reference)
#include <cuda_runtime.h>
#include <math.h>

#define NMAX 100000
#define EMAX 3200000
#define FIN  512
#define HID  16
#define NCLS 40

// Scratch (static __device__ — no allocations allowed)
__device__ float g_deg[NMAX];
__device__ float g_dinv[NMAX];
__device__ __align__(16) float g_h[NMAX * HID];    // h1, then relu(h) for layer 2
__device__ __align__(16) float g_agg[NMAX * HID];  // agg1, then agg2 (in-place reuse)

__device__ __forceinline__ void red_add_v4(float* p, float a, float b, float c, float d) {
    asm volatile("red.global.add.v4.f32 [%0], {%1,%2,%3,%4};"
                 :: "l"(p), "f"(a), "f"(b), "f"(c), "f"(d) : "memory");
}

// ---------------- degree / norm ----------------
__global__ void k_init_deg(int n) {
    int i = blockIdx.x * blockDim.x + threadIdx.x;
    if (i < n) g_deg[i] = 1.0f;  // self-loop contributes 1
}

__global__ void k_deg(const int* __restrict__ ei, int e) {
    int i = blockIdx.x * blockDim.x + threadIdx.x;
    if (i >= e) return;
    int d = ei[e + i];  // dst row (int32: JAX x64 is disabled, int64 request -> int32)
    atomicAdd(&g_deg[d], 1.0f);
}

// dinv = rsqrt(deg); also initialize agg1 with the self-loop term dinv^2 * h[n]
__global__ void k_dinv_self(int n) {
    int i = blockIdx.x * blockDim.x + threadIdx.x;
    if (i >= n) return;
    float dv = rsqrtf(g_deg[i]);
    g_dinv[i] = dv;
    float s = dv * dv;
    const float4* hp = (const float4*)&g_h[i * HID];
    float4* ap = (float4*)&g_agg[i * HID];
#pragma unroll
    for (int j = 0; j < 4; j++) {
        float4 v = hp[j];
        v.x *= s; v.y *= s; v.z *= s; v.w *= s;
        ap[j] = v;
    }
}

// ---------------- GEMM1: h = x @ W1  (N x 512 @ 512 x 16) ----------------
#define GROWS 256
#define GKT   32
__global__ __launch_bounds__(256) void k_gemm1(const float* __restrict__ x,
                                               const float* __restrict__ W1, int n) {
    __shared__ __align__(16) float xs[GKT][GROWS + 4];   // k-major (transposed) tile, padded
    __shared__ __align__(16) float ws[GKT][HID];
    int t = threadIdx.x;
    int lane = t & 31, w = t >> 5;
    int rg = t >> 2, cg = t & 3;           // 64 row-groups x 4 col-groups
    int r0 = blockIdx.x * GROWS;

    float acc[4][4];
#pragma unroll
    for (int i = 0; i < 4; i++)
#pragma unroll
        for (int j = 0; j < 4; j++) acc[i][j] = 0.0f;

    for (int kt = 0; kt < FIN; kt += GKT) {
        for (int idx = t; idx < GKT * HID; idx += 256) {
            int kk = idx >> 4, cc = idx & 15;
            ws[kk][cc] = W1[(kt + kk) * HID + cc];
        }
#pragma unroll 4
        for (int i = 0; i < GROWS / 8; i++) {
            int row = i * 8 + w;
            int gr = r0 + row;
            float v = 0.0f;
            if (gr < n) v = x[(long)gr * FIN + kt + lane];
            xs[lane][row] = v;
        }
        __syncthreads();
#pragma unroll
        for (int k = 0; k < GKT; k++) {
            float4 xv = *(const float4*)&xs[k][rg * 4];
            float4 wv = *(const float4*)&ws[k][cg * 4];
            acc[0][0] += xv.x * wv.x; acc[0][1] += xv.x * wv.y; acc[0][2] += xv.x * wv.z; acc[0][3] += xv.x * wv.w;
            acc[1][0] += xv.y * wv.x; acc[1][1] += xv.y * wv.y; acc[1][2] += xv.y * wv.z; acc[1][3] += xv.y * wv.w;
            acc[2][0] += xv.z * wv.x; acc[2][1] += xv.z * wv.y; acc[2][2] += xv.z * wv.z; acc[2][3] += xv.z * wv.w;
            acc[3][0] += xv.w * wv.x; acc[3][1] += xv.w * wv.y; acc[3][2] += xv.w * wv.z; acc[3][3] += xv.w * wv.w;
        }
        __syncthreads();
    }
#pragma unroll
    for (int i = 0; i < 4; i++) {
        int gr = r0 + rg * 4 + i;
        if (gr < n) {
            float4 o = make_float4(acc[i][0], acc[i][1], acc[i][2], acc[i][3]);
            *(float4*)&g_h[gr * HID + cg * 4] = o;
        }
    }
}

// ---------------- edge scatter: agg[dst] += dinv[src]*dinv[dst] * h[src] ----------------
__global__ __launch_bounds__(256) void k_scatter(const int* __restrict__ ei, int e) {
    int i = blockIdx.x * blockDim.x + threadIdx.x;
    if (i >= e) return;
    int s = ei[i];
    int d = ei[e + i];
    float wgt = g_dinv[s] * g_dinv[d];
    const float4* hp = (const float4*)&g_h[s * HID];
    float* ap = &g_agg[d * HID];
#pragma unroll
    for (int j = 0; j < 4; j++) {
        float4 v = hp[j];
        red_add_v4(ap + 4 * j, v.x * wgt, v.y * wgt, v.z * wgt, v.w * wgt);
    }
}

// ---------------- between layers: hr = relu(agg1 + b1); agg2_init = dinv^2 * hr ----------------
__global__ void k_relu_self(const float* __restrict__ b1, int n) {
    int i = blockIdx.x * blockDim.x + threadIdx.x;
    if (i >= n) return;
    float dv = g_dinv[i];
    float s = dv * dv;
    float4* hp = (float4*)&g_h[i * HID];
    float4* ap = (float4*)&g_agg[i * HID];
    const float4* bp = (const float4*)b1;
#pragma unroll
    for (int j = 0; j < 4; j++) {
        float4 v = ap[j];
        float4 b = bp[j];
        v.x = fmaxf(v.x + b.x, 0.0f);
        v.y = fmaxf(v.y + b.y, 0.0f);
        v.z = fmaxf(v.z + b.z, 0.0f);
        v.w = fmaxf(v.w + b.w, 0.0f);
        hp[j] = v;
        float4 o = make_float4(v.x * s, v.y * s, v.z * s, v.w * s);
        ap[j] = o;
    }
}

// ---------------- final: out = log_softmax(agg2 @ W2 + b2) ----------------
__global__ __launch_bounds__(256) void k_final(const float* __restrict__ W2,
                                               const float* __restrict__ b2,
                                               float* __restrict__ out, int n) {
    __shared__ float w2s[HID * NCLS];
    __shared__ float b2s[NCLS];
    int t = threadIdx.x;
    for (int idx = t; idx < HID * NCLS; idx += 256) w2s[idx] = W2[idx];
    if (t < NCLS) b2s[t] = b2[t];
    __syncthreads();

    int warp = t >> 5, lane = t & 31;
    int row = blockIdx.x * 8 + warp;
    if (row >= n) return;

    float a[HID];
    const float4* ap = (const float4*)&g_agg[row * HID];
#pragma unroll
    for (int j = 0; j < 4; j++) {
        float4 v = ap[j];
        a[4 * j + 0] = v.x; a[4 * j + 1] = v.y; a[4 * j + 2] = v.z; a[4 * j + 3] = v.w;
    }

    int c1 = lane;                 // cols 0..31
    float v1 = b2s[c1];
#pragma unroll
    for (int k = 0; k < HID; k++) v1 += a[k] * w2s[k * NCLS + c1];

    float v2 = __int_as_float(0xff800000);  // -inf
    if (lane < 8) {
        int c2 = 32 + lane;        // cols 32..39
        v2 = b2s[c2];
#pragma unroll
        for (int k = 0; k < HID; k++) v2 += a[k] * w2s[k * NCLS + c2];
    }

    float m = fmaxf(v1, v2);
#pragma unroll
    for (int off = 16; off >= 1; off >>= 1)
        m = fmaxf(m, __shfl_xor_sync(0xffffffffu, m, off));

    float se = __expf(v1 - m) + ((lane < 8) ? __expf(v2 - m) : 0.0f);
#pragma unroll
    for (int off = 16; off >= 1; off >>= 1)
        se += __shfl_xor_sync(0xffffffffu, se, off);

    float lse = __logf(se);
    out[row * NCLS + lane] = v1 - m - lse;
    if (lane < 8) out[row * NCLS + 32 + lane] = v2 - m - lse;
}

extern "C" void kernel_launch(void* const* d_in, const int* in_sizes, int n_in,
                              void* d_out, int out_size) {
    const float* x  = (const float*)d_in[0];
    const float* W1 = (const float*)d_in[1];
    const float* b1 = (const float*)d_in[2];
    const float* W2 = (const float*)d_in[3];
    const float* b2 = (const float*)d_in[4];
    const int*   ei = (const int*)d_in[5];   // int32: JAX x64 disabled

    int n = in_sizes[0] / FIN;
    int e = in_sizes[5] / 2;
    if (n > NMAX) n = NMAX;
    if (e > EMAX) e = EMAX;

    int nb = (n + 255) / 256;
    int eb = (e + 255) / 256;

    k_init_deg<<<nb, 256>>>(n);
    k_deg<<<eb, 256>>>(ei, e);
    k_gemm1<<<(n + GROWS - 1) / GROWS, 256>>>(x, W1, n);
    k_dinv_self<<<nb, 256>>>(n);
    k_scatter<<<eb, 256>>>(ei, e);          // layer-1 aggregation into g_agg
    k_relu_self<<<nb, 256>>>(b1, n);        // relu + layer-2 self-loop init
    k_scatter<<<eb, 256>>>(ei, e);          // layer-2 aggregation (16-wide, pre-W2)
    k_final<<<(n + 7) / 8, 256>>>(W2, b2, (float*)d_out, n);
}

// round 5
// speedup vs baseline: 1.3975x; 1.3975x over previous
#include <cuda_runtime.h>
#include <math.h>

#define NMAX 100000
#define EMAX 3200000
#define FIN  512
#define HID  16
#define NCLS 40
#define NB1024 ((NMAX + 1023) / 1024)

// ---- static scratch (no allocations allowed) ----
__device__ int   g_degi[NMAX];
__device__ int   g_incl[NMAX];
__device__ int   g_bsum[128];
__device__ int   g_bsumscan[128];
__device__ int   g_rowstart[NMAX];
__device__ int   g_cursor[NMAX];
__device__ int   g_col[EMAX];
__device__ float g_dinv[NMAX];
__device__ __align__(128) float g_h [NMAX * HID];  // hs1 = dinv * (x@W1)
__device__ __align__(128) float g_h2[NMAX * HID];  // hs2 = dinv * relu(agg1+b1)

// ---------------- degree ----------------
__global__ void k_zero_deg(int n) {
    int i = blockIdx.x * blockDim.x + threadIdx.x;
    if (i < n) g_degi[i] = 0;
}

__global__ void k_deg(const int* __restrict__ ei, int e) {
    int i = blockIdx.x * blockDim.x + threadIdx.x;
    if (i >= e) return;
    atomicAdd(&g_degi[ei[e + i]], 1);   // no return use -> REDG
}

// ---------------- scan (3-phase) ----------------
__global__ __launch_bounds__(1024) void k_scan1(int n) {
    __shared__ int sh[1024];
    int t = threadIdx.x;
    int i = blockIdx.x * 1024 + t;
    int v = (i < n) ? g_degi[i] : 0;
    sh[t] = v;
    __syncthreads();
#pragma unroll
    for (int off = 1; off < 1024; off <<= 1) {
        int u = (t >= off) ? sh[t - off] : 0;
        __syncthreads();
        sh[t] += u;
        __syncthreads();
    }
    if (i < n) g_incl[i] = sh[t];
    if (t == 1023) g_bsum[blockIdx.x] = sh[1023];
}

__global__ void k_scan2(int nb) {
    __shared__ int sh[128];
    int t = threadIdx.x;
    sh[t] = (t < nb) ? g_bsum[t] : 0;
    __syncthreads();
    if (t == 0) {
        int s = 0;
        for (int i = 0; i < nb; i++) { s += sh[i]; sh[i] = s; }
    }
    __syncthreads();
    if (t < nb) g_bsumscan[t] = sh[t];
}

__global__ void k_scan3(int n) {
    int i = blockIdx.x * blockDim.x + threadIdx.x;
    if (i >= n) return;
    int blk = i >> 10;
    int off = blk ? g_bsumscan[blk - 1] : 0;
    int dg  = g_degi[i];
    int start = off + g_incl[i] - dg;
    g_rowstart[i] = start;
    g_cursor[i]   = start;
    g_dinv[i] = rsqrtf((float)(dg + 1));   // self-loop adds 1
}

// ---------------- CSR fill ----------------
__global__ void k_fill(const int* __restrict__ ei, int e) {
    int i = blockIdx.x * blockDim.x + threadIdx.x;
    if (i >= e) return;
    int s = ei[i];
    int d = ei[e + i];
    int p = atomicAdd(&g_cursor[d], 1);
    g_col[p] = s;
}

// ---------------- GEMM1: hs1 = dinv * (x @ W1) ----------------
#define GROWS 256
#define GKT   32
__global__ __launch_bounds__(256) void k_gemm1(const float* __restrict__ x,
                                               const float* __restrict__ W1, int n) {
    __shared__ __align__(16) float xs[GKT][GROWS + 4];
    __shared__ __align__(16) float ws[GKT][HID];
    int t = threadIdx.x;
    int lane = t & 31, w = t >> 5;
    int rg = t >> 2, cg = t & 3;
    int r0 = blockIdx.x * GROWS;

    float acc[4][4];
#pragma unroll
    for (int i = 0; i < 4; i++)
#pragma unroll
        for (int j = 0; j < 4; j++) acc[i][j] = 0.0f;

    for (int kt = 0; kt < FIN; kt += GKT) {
        for (int idx = t; idx < GKT * HID; idx += 256) {
            int kk = idx >> 4, cc = idx & 15;
            ws[kk][cc] = W1[(kt + kk) * HID + cc];
        }
#pragma unroll 4
        for (int i = 0; i < GROWS / 8; i++) {
            int row = i * 8 + w;
            int gr = r0 + row;
            float v = 0.0f;
            if (gr < n) v = x[(long)gr * FIN + kt + lane];
            xs[lane][row] = v;
        }
        __syncthreads();
#pragma unroll
        for (int k = 0; k < GKT; k++) {
            float4 xv = *(const float4*)&xs[k][rg * 4];
            float4 wv = *(const float4*)&ws[k][cg * 4];
            acc[0][0] += xv.x * wv.x; acc[0][1] += xv.x * wv.y; acc[0][2] += xv.x * wv.z; acc[0][3] += xv.x * wv.w;
            acc[1][0] += xv.y * wv.x; acc[1][1] += xv.y * wv.y; acc[1][2] += xv.y * wv.z; acc[1][3] += xv.y * wv.w;
            acc[2][0] += xv.z * wv.x; acc[2][1] += xv.z * wv.y; acc[2][2] += xv.z * wv.z; acc[2][3] += xv.z * wv.w;
            acc[3][0] += xv.w * wv.x; acc[3][1] += xv.w * wv.y; acc[3][2] += xv.w * wv.z; acc[3][3] += xv.w * wv.w;
        }
        __syncthreads();
    }
#pragma unroll
    for (int i = 0; i < 4; i++) {
        int gr = r0 + rg * 4 + i;
        if (gr < n) {
            float dv = g_dinv[gr];
            float4 o = make_float4(acc[i][0] * dv, acc[i][1] * dv, acc[i][2] * dv, acc[i][3] * dv);
            *(float4*)&g_h[gr * HID + cg * 4] = o;
        }
    }
}

// ---------------- gather 1: hs2 = dinv * relu(dinv*(sum hs1[nbr] + hs1[self]) + b1) ----------------
__global__ __launch_bounds__(256) void k_gather1(const float* __restrict__ b1, int n) {
    int v = (blockIdx.x * 256 + threadIdx.x) >> 5;
    if (v >= n) return;
    int lane = threadIdx.x & 31;
    int half = lane >> 4, f = lane & 15;

    int beg = g_rowstart[v];
    int dg  = g_degi[v];

    float acc = 0.0f;
    int j = half;
    for (; j + 2 < dg; j += 4) {
        int s0 = __ldg(&g_col[beg + j]);
        int s1 = __ldg(&g_col[beg + j + 2]);
        acc += g_h[s0 * HID + f] + g_h[s1 * HID + f];
    }
    for (; j < dg; j += 2) {
        int s = __ldg(&g_col[beg + j]);
        acc += g_h[s * HID + f];
    }
    acc += __shfl_xor_sync(0xffffffffu, acc, 16);

    float dv   = g_dinv[v];
    float self = g_h[v * HID + f];
    float val  = dv * (acc + self);
    float h2   = fmaxf(val + __ldg(&b1[f]), 0.0f);
    if (lane < 16) g_h2[v * HID + f] = dv * h2;
}

// ---------------- gather 2 + W2 + log_softmax ----------------
__global__ __launch_bounds__(256) void k_gather2_final(const float* __restrict__ W2,
                                                       const float* __restrict__ b2,
                                                       float* __restrict__ out, int n) {
    __shared__ float w2s[HID * NCLS];
    __shared__ float b2s[NCLS];
    int t = threadIdx.x;
    for (int idx = t; idx < HID * NCLS; idx += 256) w2s[idx] = W2[idx];
    if (t < NCLS) b2s[t] = b2[t];
    __syncthreads();

    int v = (blockIdx.x * 256 + t) >> 5;
    if (v >= n) return;
    int lane = t & 31;
    int half = lane >> 4, f = lane & 15;

    int beg = g_rowstart[v];
    int dg  = g_degi[v];

    float acc = 0.0f;
    int j = half;
    for (; j + 2 < dg; j += 4) {
        int s0 = __ldg(&g_col[beg + j]);
        int s1 = __ldg(&g_col[beg + j + 2]);
        acc += g_h2[s0 * HID + f] + g_h2[s1 * HID + f];
    }
    for (; j < dg; j += 2) {
        int s = __ldg(&g_col[beg + j]);
        acc += g_h2[s * HID + f];
    }
    acc += __shfl_xor_sync(0xffffffffu, acc, 16);

    float dv  = g_dinv[v];
    float val = dv * (acc + g_h2[v * HID + f]);   // agg2 component f, valid lanes 0-15

    float a[HID];
#pragma unroll
    for (int k = 0; k < HID; k++) a[k] = __shfl_sync(0xffffffffu, val, k);

    float v1 = b2s[lane];
#pragma unroll
    for (int k = 0; k < HID; k++) v1 += a[k] * w2s[k * NCLS + lane];

    float v2 = __int_as_float(0xff800000);  // -inf
    if (lane < 8) {
        int c2 = 32 + lane;
        v2 = b2s[c2];
#pragma unroll
        for (int k = 0; k < HID; k++) v2 += a[k] * w2s[k * NCLS + c2];
    }

    float m = fmaxf(v1, v2);
#pragma unroll
    for (int off = 16; off >= 1; off >>= 1)
        m = fmaxf(m, __shfl_xor_sync(0xffffffffu, m, off));

    float se = __expf(v1 - m) + ((lane < 8) ? __expf(v2 - m) : 0.0f);
#pragma unroll
    for (int off = 16; off >= 1; off >>= 1)
        se += __shfl_xor_sync(0xffffffffu, se, off);

    float lse = __logf(se);
    out[v * NCLS + lane] = v1 - m - lse;
    if (lane < 8) out[v * NCLS + 32 + lane] = v2 - m - lse;
}

extern "C" void kernel_launch(void* const* d_in, const int* in_sizes, int n_in,
                              void* d_out, int out_size) {
    const float* x  = (const float*)d_in[0];
    const float* W1 = (const float*)d_in[1];
    const float* b1 = (const float*)d_in[2];
    const float* W2 = (const float*)d_in[3];
    const float* b2 = (const float*)d_in[4];
    const int*   ei = (const int*)d_in[5];   // int32: JAX x64 disabled

    int n = in_sizes[0] / FIN;
    int e = in_sizes[5] / 2;
    if (n > NMAX) n = NMAX;
    if (e > EMAX) e = EMAX;

    int nb  = (n + 255) / 256;
    int eb  = (e + 255) / 256;
    int nbs = (n + 1023) / 1024;
    int gwb = (n * 32 + 255) / 256;   // warp-per-node grids

    k_zero_deg<<<nb, 256>>>(n);
    k_deg<<<eb, 256>>>(ei, e);
    k_scan1<<<nbs, 1024>>>(n);
    k_scan2<<<1, 128>>>(nbs);
    k_scan3<<<nb, 256>>>(n);
    k_gemm1<<<(n + GROWS - 1) / GROWS, 256>>>(x, W1, n);
    k_fill<<<eb, 256>>>(ei, e);
    k_gather1<<<gwb, 256>>>(b1, n);
    k_gather2_final<<<gwb, 256>>>(W2, b2, (float*)d_out, n);
}

// round 6
// speedup vs baseline: 1.4839x; 1.0618x over previous
#include <cuda_runtime.h>
#include <math.h>

#define NMAX 100000
#define EMAX 3200000
#define FIN  512
#define HID  16
#define NCLS 40

// ---- static scratch (no allocations allowed) ----
__device__ int   g_degi[NMAX];
__device__ int   g_incl[NMAX];
__device__ int   g_bsum[128];
__device__ int   g_bsumscan[128];
__device__ int   g_rowstart[NMAX];
__device__ int   g_cursor[NMAX];
__device__ int   g_col[EMAX];
__device__ float g_dinv[NMAX];
__device__ __align__(128) float g_h [NMAX * HID];  // hs1 = dinv * (x@W1)
__device__ __align__(128) float g_h2[NMAX * HID];  // hs2 = dinv * relu(agg1+b1)

// packed f32x2 helpers (Blackwell)
#define PACK2(d, lo, hi) \
    asm("mov.b64 %0, {%1, %2};" : "=l"(d) : "f"(lo), "f"(hi))
#define UNPACK2(lo, hi, s) \
    asm("mov.b64 {%0, %1}, %2;" : "=f"(lo), "=f"(hi) : "l"(s))
#define FMA2(d, a, b, c) \
    asm("fma.rn.f32x2 %0, %1, %2, %3;" : "=l"(d) : "l"(a), "l"(b), "l"(c))

// ---------------- degree ----------------
__global__ void k_zero_deg(int n) {
    int i = blockIdx.x * blockDim.x + threadIdx.x;
    if (i < n) g_degi[i] = 0;
}

__global__ void k_deg(const int* __restrict__ ei, int e) {
    int i = blockIdx.x * blockDim.x + threadIdx.x;
    if (i >= e) return;
    atomicAdd(&g_degi[ei[e + i]], 1);   // no return use -> REDG
}

// ---------------- scan (3-phase, shfl-based) ----------------
__global__ __launch_bounds__(1024) void k_scan1(int n) {
    __shared__ int wsum[32];
    int t = threadIdx.x, lane = t & 31, w = t >> 5;
    int i = blockIdx.x * 1024 + t;
    int x = (i < n) ? g_degi[i] : 0;
#pragma unroll
    for (int off = 1; off < 32; off <<= 1) {
        int u = __shfl_up_sync(0xffffffffu, x, off);
        if (lane >= off) x += u;
    }
    if (lane == 31) wsum[w] = x;
    __syncthreads();
    if (w == 0) {
        int y = wsum[lane];
#pragma unroll
        for (int off = 1; off < 32; off <<= 1) {
            int u = __shfl_up_sync(0xffffffffu, y, off);
            if (lane >= off) y += u;
        }
        wsum[lane] = y;
    }
    __syncthreads();
    if (w > 0) x += wsum[w - 1];
    if (i < n) g_incl[i] = x;
    if (t == 1023) g_bsum[blockIdx.x] = x;
}

__global__ void k_scan2(int nb) {
    __shared__ int wsum[4];
    int t = threadIdx.x, lane = t & 31, w = t >> 5;
    int x = (t < nb) ? g_bsum[t] : 0;
#pragma unroll
    for (int off = 1; off < 32; off <<= 1) {
        int u = __shfl_up_sync(0xffffffffu, x, off);
        if (lane >= off) x += u;
    }
    if (lane == 31) wsum[w] = x;
    __syncthreads();
    if (t == 0) {
        int s = 0;
#pragma unroll
        for (int i = 0; i < 4; i++) { s += wsum[i]; wsum[i] = s; }
    }
    __syncthreads();
    if (w > 0) x += wsum[w - 1];
    if (t < nb) g_bsumscan[t] = x;
}

__global__ void k_scan3(int n) {
    int i = blockIdx.x * blockDim.x + threadIdx.x;
    if (i >= n) return;
    int blk = i >> 10;
    int off = blk ? g_bsumscan[blk - 1] : 0;
    int dg  = g_degi[i];
    int start = off + g_incl[i] - dg;
    g_rowstart[i] = start;
    g_cursor[i]   = start;
    g_dinv[i] = rsqrtf((float)(dg + 1));   // self-loop adds 1
}

// ---------------- CSR fill ----------------
__global__ void k_fill(const int* __restrict__ ei, int e) {
    int i = blockIdx.x * blockDim.x + threadIdx.x;
    if (i >= e) return;
    int s = ei[i];
    int d = ei[e + i];
    int p = atomicAdd(&g_cursor[d], 1);
    g_col[p] = s;
}

// ---------------- GEMM1: hs1 = dinv * (x @ W1), packed f32x2 ----------------
#define GROWS 256
#define GKT   32
__global__ __launch_bounds__(256) void k_gemm1(const float* __restrict__ x,
                                               const float* __restrict__ W1, int n) {
    __shared__ __align__(16) float xs[GKT][GROWS + 4];
    __shared__ __align__(16) float ws[GKT][HID];
    int t = threadIdx.x;
    int lane = t & 31, w = t >> 5;
    int rg = t >> 2, cg = t & 3;
    int r0 = blockIdx.x * GROWS;

    unsigned long long acc01[4], acc23[4];
#pragma unroll
    for (int j = 0; j < 4; j++) { acc01[j] = 0ull; acc23[j] = 0ull; }

    for (int kt = 0; kt < FIN; kt += GKT) {
        for (int idx = t; idx < GKT * HID; idx += 256) {
            int kk = idx >> 4, cc = idx & 15;
            ws[kk][cc] = W1[(kt + kk) * HID + cc];
        }
#pragma unroll 4
        for (int i = 0; i < GROWS / 8; i++) {
            int row = i * 8 + w;
            int gr = r0 + row;
            float v = 0.0f;
            if (gr < n) v = x[(long)gr * FIN + kt + lane];
            xs[lane][row] = v;
        }
        __syncthreads();
#pragma unroll
        for (int k = 0; k < GKT; k++) {
            float4 xv = *(const float4*)&xs[k][rg * 4];
            float4 wv = *(const float4*)&ws[k][cg * 4];
            unsigned long long px01, px23, pw0, pw1, pw2, pw3;
            PACK2(px01, xv.x, xv.y);
            PACK2(px23, xv.z, xv.w);
            PACK2(pw0, wv.x, wv.x);
            PACK2(pw1, wv.y, wv.y);
            PACK2(pw2, wv.z, wv.z);
            PACK2(pw3, wv.w, wv.w);
            FMA2(acc01[0], px01, pw0, acc01[0]);
            FMA2(acc23[0], px23, pw0, acc23[0]);
            FMA2(acc01[1], px01, pw1, acc01[1]);
            FMA2(acc23[1], px23, pw1, acc23[1]);
            FMA2(acc01[2], px01, pw2, acc01[2]);
            FMA2(acc23[2], px23, pw2, acc23[2]);
            FMA2(acc01[3], px01, pw3, acc01[3]);
            FMA2(acc23[3], px23, pw3, acc23[3]);
        }
        __syncthreads();
    }

    float acc[4][4];
#pragma unroll
    for (int j = 0; j < 4; j++) {
        UNPACK2(acc[0][j], acc[1][j], acc01[j]);
        UNPACK2(acc[2][j], acc[3][j], acc23[j]);
    }
#pragma unroll
    for (int i = 0; i < 4; i++) {
        int gr = r0 + rg * 4 + i;
        if (gr < n) {
            float dv = g_dinv[gr];
            float4 o = make_float4(acc[i][0] * dv, acc[i][1] * dv,
                                   acc[i][2] * dv, acc[i][3] * dv);
            *(float4*)&g_h[gr * HID + cg * 4] = o;
        }
    }
}

// ---------------- gather 1: hs2 = dinv * relu(dinv*(sum hs1[nbr] + hs1[self]) + b1) ----------------
// lane layout: slot = lane>>3 (4 neighbor slots), fp = lane&7 (8 float2 feature lanes)
__global__ __launch_bounds__(256) void k_gather1(const float* __restrict__ b1, int n) {
    int v = blockIdx.x * 8 + (threadIdx.x >> 5);
    if (v >= n) return;
    int lane = threadIdx.x & 31;
    int slot = lane >> 3, fp = lane & 7;

    int beg = g_rowstart[v];
    int dg  = g_degi[v];

    float ax = 0.0f, ay = 0.0f;
    int j = slot;
    for (; j + 4 < dg; j += 8) {
        int s0 = __ldg(&g_col[beg + j]);
        int s1 = __ldg(&g_col[beg + j + 4]);
        float2 h0 = *(const float2*)&g_h[s0 * HID + fp * 2];
        float2 h1 = *(const float2*)&g_h[s1 * HID + fp * 2];
        ax += h0.x + h1.x; ay += h0.y + h1.y;
    }
    if (j < dg) {
        int s = __ldg(&g_col[beg + j]);
        float2 h0 = *(const float2*)&g_h[s * HID + fp * 2];
        ax += h0.x; ay += h0.y;
    }
    ax += __shfl_xor_sync(0xffffffffu, ax, 8);
    ay += __shfl_xor_sync(0xffffffffu, ay, 8);
    ax += __shfl_xor_sync(0xffffffffu, ax, 16);
    ay += __shfl_xor_sync(0xffffffffu, ay, 16);

    float dv = g_dinv[v];
    float2 self = *(const float2*)&g_h[v * HID + fp * 2];
    float2 bb   = *(const float2*)&b1[fp * 2];
    float hx = fmaxf(dv * (ax + self.x) + bb.x, 0.0f);
    float hy = fmaxf(dv * (ay + self.y) + bb.y, 0.0f);
    if (lane < 8) {
        float2 o = make_float2(dv * hx, dv * hy);
        *(float2*)&g_h2[v * HID + fp * 2] = o;
    }
}

// ---------------- gather 2 + W2 + log_softmax ----------------
__global__ __launch_bounds__(256) void k_gather2_final(const float* __restrict__ W2,
                                                       const float* __restrict__ b2,
                                                       float* __restrict__ out, int n) {
    __shared__ float w2s[HID * NCLS];
    __shared__ float b2s[NCLS];
    int t = threadIdx.x;
    for (int idx = t; idx < HID * NCLS; idx += 256) w2s[idx] = W2[idx];
    if (t < NCLS) b2s[t] = b2[t];
    __syncthreads();

    int v = blockIdx.x * 8 + (t >> 5);
    if (v >= n) return;
    int lane = t & 31;
    int slot = lane >> 3, fp = lane & 7;

    int beg = g_rowstart[v];
    int dg  = g_degi[v];

    float ax = 0.0f, ay = 0.0f;
    int j = slot;
    for (; j + 4 < dg; j += 8) {
        int s0 = __ldg(&g_col[beg + j]);
        int s1 = __ldg(&g_col[beg + j + 4]);
        float2 h0 = *(const float2*)&g_h2[s0 * HID + fp * 2];
        float2 h1 = *(const float2*)&g_h2[s1 * HID + fp * 2];
        ax += h0.x + h1.x; ay += h0.y + h1.y;
    }
    if (j < dg) {
        int s = __ldg(&g_col[beg + j]);
        float2 h0 = *(const float2*)&g_h2[s * HID + fp * 2];
        ax += h0.x; ay += h0.y;
    }
    ax += __shfl_xor_sync(0xffffffffu, ax, 8);
    ay += __shfl_xor_sync(0xffffffffu, ay, 8);
    ax += __shfl_xor_sync(0xffffffffu, ax, 16);
    ay += __shfl_xor_sync(0xffffffffu, ay, 16);

    float dv = g_dinv[v];
    float2 self = *(const float2*)&g_h2[v * HID + fp * 2];
    float vx = dv * (ax + self.x);   // agg2 feature 2*fp
    float vy = dv * (ay + self.y);   // agg2 feature 2*fp+1

    float a[HID];
#pragma unroll
    for (int k = 0; k < HID; k++)
        a[k] = __shfl_sync(0xffffffffu, (k & 1) ? vy : vx, k >> 1);

    float v1 = b2s[lane];
#pragma unroll
    for (int k = 0; k < HID; k++) v1 += a[k] * w2s[k * NCLS + lane];

    float v2 = __int_as_float(0xff800000);  // -inf
    if (lane < 8) {
        int c2 = 32 + lane;
        v2 = b2s[c2];
#pragma unroll
        for (int k = 0; k < HID; k++) v2 += a[k] * w2s[k * NCLS + c2];
    }

    float m = fmaxf(v1, v2);
#pragma unroll
    for (int off = 16; off >= 1; off >>= 1)
        m = fmaxf(m, __shfl_xor_sync(0xffffffffu, m, off));

    float se = __expf(v1 - m) + ((lane < 8) ? __expf(v2 - m) : 0.0f);
#pragma unroll
    for (int off = 16; off >= 1; off >>= 1)
        se += __shfl_xor_sync(0xffffffffu, se, off);

    float lse = __logf(se);
    out[v * NCLS + lane] = v1 - m - lse;
    if (lane < 8) out[v * NCLS + 32 + lane] = v2 - m - lse;
}

extern "C" void kernel_launch(void* const* d_in, const int* in_sizes, int n_in,
                              void* d_out, int out_size) {
    const float* x  = (const float*)d_in[0];
    const float* W1 = (const float*)d_in[1];
    const float* b1 = (const float*)d_in[2];
    const float* W2 = (const float*)d_in[3];
    const float* b2 = (const float*)d_in[4];
    const int*   ei = (const int*)d_in[5];   // int32: JAX x64 disabled

    int n = in_sizes[0] / FIN;
    int e = in_sizes[5] / 2;
    if (n > NMAX) n = NMAX;
    if (e > EMAX) e = EMAX;

    int nb  = (n + 255) / 256;
    int eb  = (e + 255) / 256;
    int nbs = (n + 1023) / 1024;
    int gnb = (n + 7) / 8;             // warp-per-node grids

    k_zero_deg<<<nb, 256>>>(n);
    k_deg<<<eb, 256>>>(ei, e);
    k_scan1<<<nbs, 1024>>>(n);
    k_scan2<<<1, 128>>>(nbs);
    k_scan3<<<nb, 256>>>(n);
    k_gemm1<<<(n + GROWS - 1) / GROWS, 256>>>(x, W1, n);
    k_fill<<<eb, 256>>>(ei, e);
    k_gather1<<<gnb, 256>>>(b1, n);
    k_gather2_final<<<gnb, 256>>>(W2, b2, (float*)d_out, n);
}

// round 7
// speedup vs baseline: 1.6859x; 1.1361x over previous
#include <cuda_runtime.h>
#include <math.h>

#define NMAX 100000
#define EMAX 3200000
#define FIN  512
#define HID  16
#define NCLS 40

// ---- static scratch (no allocations allowed) ----
__device__ int   g_degi[NMAX];
__device__ int   g_incl[NMAX];
__device__ int   g_bsum[128];
__device__ int   g_bsumscan[128];
__device__ int   g_rowstart[NMAX];
__device__ int   g_cursor[NMAX];
__device__ int   g_col[EMAX];
__device__ float g_dinv[NMAX];
__device__ __align__(128) float g_h [NMAX * HID];  // raw h = x@W1 (unscaled)
__device__ __align__(128) float g_h2[NMAX * HID];  // hs2 = dinv * relu(agg1+b1)

// packed f32x2 helpers (Blackwell)
#define PACK2(d, lo, hi) \
    asm("mov.b64 %0, {%1, %2};" : "=l"(d) : "f"(lo), "f"(hi))
#define UNPACK2(lo, hi, s) \
    asm("mov.b64 {%0, %1}, %2;" : "=f"(lo), "=f"(hi) : "l"(s))
#define FMA2(d, a, b, c) \
    asm("fma.rn.f32x2 %0, %1, %2, %3;" : "=l"(d) : "l"(a), "l"(b), "l"(c))

// ---------------- degree ----------------
__global__ void k_zero_deg(int n) {
    int i = blockIdx.x * blockDim.x + threadIdx.x;
    if (i < n) g_degi[i] = 0;
}

__global__ void k_deg(const int* __restrict__ ei, int e) {
    int i = blockIdx.x * blockDim.x + threadIdx.x;
    if (i >= e) return;
    atomicAdd(&g_degi[ei[e + i]], 1);   // no return use -> REDG
}

// ---------------- scan (3-phase, shfl-based); scan1 also computes dinv ----------------
__global__ __launch_bounds__(1024) void k_scan1(int n) {
    __shared__ int wsum[32];
    int t = threadIdx.x, lane = t & 31, w = t >> 5;
    int i = blockIdx.x * 1024 + t;
    int dg = (i < n) ? g_degi[i] : 0;
    if (i < n) g_dinv[i] = rsqrtf((float)(dg + 1));   // self-loop adds 1
    int x = dg;
#pragma unroll
    for (int off = 1; off < 32; off <<= 1) {
        int u = __shfl_up_sync(0xffffffffu, x, off);
        if (lane >= off) x += u;
    }
    if (lane == 31) wsum[w] = x;
    __syncthreads();
    if (w == 0) {
        int y = wsum[lane];
#pragma unroll
        for (int off = 1; off < 32; off <<= 1) {
            int u = __shfl_up_sync(0xffffffffu, y, off);
            if (lane >= off) y += u;
        }
        wsum[lane] = y;
    }
    __syncthreads();
    if (w > 0) x += wsum[w - 1];
    if (i < n) g_incl[i] = x;
    if (t == 1023) g_bsum[blockIdx.x] = x;
}

__global__ void k_scan2(int nb) {
    __shared__ int wsum[4];
    int t = threadIdx.x, lane = t & 31, w = t >> 5;
    int x = (t < nb) ? g_bsum[t] : 0;
#pragma unroll
    for (int off = 1; off < 32; off <<= 1) {
        int u = __shfl_up_sync(0xffffffffu, x, off);
        if (lane >= off) x += u;
    }
    if (lane == 31) wsum[w] = x;
    __syncthreads();
    if (t == 0) {
        int s = 0;
#pragma unroll
        for (int i = 0; i < 4; i++) { s += wsum[i]; wsum[i] = s; }
    }
    __syncthreads();
    if (w > 0) x += wsum[w - 1];
    if (t < nb) g_bsumscan[t] = x;
}

__global__ void k_scan3(int n) {
    int i = blockIdx.x * blockDim.x + threadIdx.x;
    if (i >= n) return;
    int blk = i >> 10;
    int off = blk ? g_bsumscan[blk - 1] : 0;
    int start = off + g_incl[i] - g_degi[i];
    g_rowstart[i] = start;
    g_cursor[i]   = start;
}

// ---------------- CSR fill ----------------
__global__ void k_fill(const int* __restrict__ ei, int e) {
    int i = blockIdx.x * blockDim.x + threadIdx.x;
    if (i >= e) return;
    int s = ei[i];
    int d = ei[e + i];
    int p = atomicAdd(&g_cursor[d], 1);
    g_col[p] = s;
}

// ---------------- GEMM1: h = x @ W1 (raw, packed f32x2) ----------------
#define GROWS 256
#define GKT   32
__global__ __launch_bounds__(256) void k_gemm1(const float* __restrict__ x,
                                               const float* __restrict__ W1, int n) {
    __shared__ __align__(16) float xs[GKT][GROWS + 4];
    __shared__ __align__(16) float ws[GKT][HID];
    int t = threadIdx.x;
    int lane = t & 31, w = t >> 5;
    int rg = t >> 2, cg = t & 3;
    int r0 = blockIdx.x * GROWS;

    unsigned long long acc01[4], acc23[4];
#pragma unroll
    for (int j = 0; j < 4; j++) { acc01[j] = 0ull; acc23[j] = 0ull; }

    for (int kt = 0; kt < FIN; kt += GKT) {
        for (int idx = t; idx < GKT * HID; idx += 256) {
            int kk = idx >> 4, cc = idx & 15;
            ws[kk][cc] = W1[(kt + kk) * HID + cc];
        }
#pragma unroll 4
        for (int i = 0; i < GROWS / 8; i++) {
            int row = i * 8 + w;
            int gr = r0 + row;
            float v = 0.0f;
            if (gr < n) v = x[(long)gr * FIN + kt + lane];
            xs[lane][row] = v;
        }
        __syncthreads();
#pragma unroll
        for (int k = 0; k < GKT; k++) {
            float4 xv = *(const float4*)&xs[k][rg * 4];
            float4 wv = *(const float4*)&ws[k][cg * 4];
            unsigned long long px01, px23, pw0, pw1, pw2, pw3;
            PACK2(px01, xv.x, xv.y);
            PACK2(px23, xv.z, xv.w);
            PACK2(pw0, wv.x, wv.x);
            PACK2(pw1, wv.y, wv.y);
            PACK2(pw2, wv.z, wv.z);
            PACK2(pw3, wv.w, wv.w);
            FMA2(acc01[0], px01, pw0, acc01[0]);
            FMA2(acc23[0], px23, pw0, acc23[0]);
            FMA2(acc01[1], px01, pw1, acc01[1]);
            FMA2(acc23[1], px23, pw1, acc23[1]);
            FMA2(acc01[2], px01, pw2, acc01[2]);
            FMA2(acc23[2], px23, pw2, acc23[2]);
            FMA2(acc01[3], px01, pw3, acc01[3]);
            FMA2(acc23[3], px23, pw3, acc23[3]);
        }
        __syncthreads();
    }

    float acc[4][4];
#pragma unroll
    for (int j = 0; j < 4; j++) {
        UNPACK2(acc[0][j], acc[1][j], acc01[j]);
        UNPACK2(acc[2][j], acc[3][j], acc23[j]);
    }
#pragma unroll
    for (int i = 0; i < 4; i++) {
        int gr = r0 + rg * 4 + i;
        if (gr < n) {
            float4 o = make_float4(acc[i][0], acc[i][1], acc[i][2], acc[i][3]);
            *(float4*)&g_h[gr * HID + cg * 4] = o;
        }
    }
}

// ---------------- gather 1: hs2 = dv * relu(dv*Σ dinv_s h_s + dv^2 h_v + b1) ----------------
// lane layout: slot = lane>>3 (4 neighbor slots), fp = lane&7 (8 float2 feature lanes)
__global__ __launch_bounds__(256) void k_gather1(const float* __restrict__ b1, int n) {
    int v = blockIdx.x * 8 + (threadIdx.x >> 5);
    if (v >= n) return;
    int lane = threadIdx.x & 31;
    int slot = lane >> 3, fp = lane & 7;

    int beg = g_rowstart[v];
    int dg  = g_degi[v];

    float ax = 0.0f, ay = 0.0f;
    int j = slot;
    for (; j + 4 < dg; j += 8) {
        int s0 = __ldg(&g_col[beg + j]);
        int s1 = __ldg(&g_col[beg + j + 4]);
        float w0 = __ldg(&g_dinv[s0]);
        float w1 = __ldg(&g_dinv[s1]);
        float2 h0 = *(const float2*)&g_h[s0 * HID + fp * 2];
        float2 h1 = *(const float2*)&g_h[s1 * HID + fp * 2];
        ax += w0 * h0.x + w1 * h1.x;
        ay += w0 * h0.y + w1 * h1.y;
    }
    if (j < dg) {
        int s = __ldg(&g_col[beg + j]);
        float w0 = __ldg(&g_dinv[s]);
        float2 h0 = *(const float2*)&g_h[s * HID + fp * 2];
        ax += w0 * h0.x; ay += w0 * h0.y;
    }
    ax += __shfl_xor_sync(0xffffffffu, ax, 8);
    ay += __shfl_xor_sync(0xffffffffu, ay, 8);
    ax += __shfl_xor_sync(0xffffffffu, ax, 16);
    ay += __shfl_xor_sync(0xffffffffu, ay, 16);

    float dv  = g_dinv[v];
    float dv2 = dv * dv;
    float2 self = *(const float2*)&g_h[v * HID + fp * 2];
    float2 bb   = *(const float2*)&b1[fp * 2];
    float hx = fmaxf(dv * ax + dv2 * self.x + bb.x, 0.0f);
    float hy = fmaxf(dv * ay + dv2 * self.y + bb.y, 0.0f);
    if (lane < 8) {
        float2 o = make_float2(dv * hx, dv * hy);
        *(float2*)&g_h2[v * HID + fp * 2] = o;
    }
}

// ---------------- gather 2 + W2 + log_softmax ----------------
__global__ __launch_bounds__(256) void k_gather2_final(const float* __restrict__ W2,
                                                       const float* __restrict__ b2,
                                                       float* __restrict__ out, int n) {
    __shared__ float w2s[HID * NCLS];
    __shared__ float b2s[NCLS];
    int t = threadIdx.x;
    for (int idx = t; idx < HID * NCLS; idx += 256) w2s[idx] = W2[idx];
    if (t < NCLS) b2s[t] = b2[t];
    __syncthreads();

    int v = blockIdx.x * 8 + (t >> 5);
    if (v >= n) return;
    int lane = t & 31;
    int slot = lane >> 3, fp = lane & 7;

    int beg = g_rowstart[v];
    int dg  = g_degi[v];

    float ax = 0.0f, ay = 0.0f;
    int j = slot;
    for (; j + 4 < dg; j += 8) {
        int s0 = __ldg(&g_col[beg + j]);
        int s1 = __ldg(&g_col[beg + j + 4]);
        float2 h0 = *(const float2*)&g_h2[s0 * HID + fp * 2];
        float2 h1 = *(const float2*)&g_h2[s1 * HID + fp * 2];
        ax += h0.x + h1.x; ay += h0.y + h1.y;
    }
    if (j < dg) {
        int s = __ldg(&g_col[beg + j]);
        float2 h0 = *(const float2*)&g_h2[s * HID + fp * 2];
        ax += h0.x; ay += h0.y;
    }
    ax += __shfl_xor_sync(0xffffffffu, ax, 8);
    ay += __shfl_xor_sync(0xffffffffu, ay, 8);
    ax += __shfl_xor_sync(0xffffffffu, ax, 16);
    ay += __shfl_xor_sync(0xffffffffu, ay, 16);

    float dv = g_dinv[v];
    float2 self = *(const float2*)&g_h2[v * HID + fp * 2];
    float vx = dv * (ax + self.x);   // agg2 feature 2*fp
    float vy = dv * (ay + self.y);   // agg2 feature 2*fp+1

    float a[HID];
#pragma unroll
    for (int k = 0; k < HID; k++)
        a[k] = __shfl_sync(0xffffffffu, (k & 1) ? vy : vx, k >> 1);

    float v1 = b2s[lane];
#pragma unroll
    for (int k = 0; k < HID; k++) v1 += a[k] * w2s[k * NCLS + lane];

    float v2 = __int_as_float(0xff800000);  // -inf
    if (lane < 8) {
        int c2 = 32 + lane;
        v2 = b2s[c2];
#pragma unroll
        for (int k = 0; k < HID; k++) v2 += a[k] * w2s[k * NCLS + c2];
    }

    float m = fmaxf(v1, v2);
#pragma unroll
    for (int off = 16; off >= 1; off >>= 1)
        m = fmaxf(m, __shfl_xor_sync(0xffffffffu, m, off));

    float se = __expf(v1 - m) + ((lane < 8) ? __expf(v2 - m) : 0.0f);
#pragma unroll
    for (int off = 16; off >= 1; off >>= 1)
        se += __shfl_xor_sync(0xffffffffu, se, off);

    float lse = __logf(se);
    out[v * NCLS + lane] = v1 - m - lse;
    if (lane < 8) out[v * NCLS + 32 + lane] = v2 - m - lse;
}

extern "C" void kernel_launch(void* const* d_in, const int* in_sizes, int n_in,
                              void* d_out, int out_size) {
    const float* x  = (const float*)d_in[0];
    const float* W1 = (const float*)d_in[1];
    const float* b1 = (const float*)d_in[2];
    const float* W2 = (const float*)d_in[3];
    const float* b2 = (const float*)d_in[4];
    const int*   ei = (const int*)d_in[5];   // int32: JAX x64 disabled

    int n = in_sizes[0] / FIN;
    int e = in_sizes[5] / 2;
    if (n > NMAX) n = NMAX;
    if (e > EMAX) e = EMAX;

    int nb  = (n + 255) / 256;
    int eb  = (e + 255) / 256;
    int nbs = (n + 1023) / 1024;
    int gnb = (n + 7) / 8;              // warp-per-node grids
    int ggb = (n + GROWS - 1) / GROWS;

    // One-time host-side stream/event setup (first call is outside capture).
    static cudaStream_t s2 = nullptr;
    static cudaEvent_t  evF = nullptr, evJ = nullptr;
    static int          tried = 0;
    if (!tried) {
        tried = 1;
        if (cudaStreamCreateWithFlags(&s2, cudaStreamNonBlocking) != cudaSuccess) s2 = nullptr;
        if (s2) {
            if (cudaEventCreateWithFlags(&evF, cudaEventDisableTiming) != cudaSuccess ||
                cudaEventCreateWithFlags(&evJ, cudaEventDisableTiming) != cudaSuccess) {
                s2 = nullptr;
            }
        }
    }

    if (s2) {
        // Fork: gemm1 runs on s2, overlapping the edge-prep chain on stream 0.
        cudaEventRecord(evF, 0);
        cudaStreamWaitEvent(s2, evF, 0);
        k_gemm1<<<ggb, 256, 0, s2>>>(x, W1, n);
        cudaEventRecord(evJ, s2);

        k_zero_deg<<<nb, 256>>>(n);
        k_deg<<<eb, 256>>>(ei, e);
        k_scan1<<<nbs, 1024>>>(n);
        k_scan2<<<1, 128>>>(nbs);
        k_scan3<<<nb, 256>>>(n);
        k_fill<<<eb, 256>>>(ei, e);

        cudaStreamWaitEvent(0, evJ, 0);   // join before gather1
    } else {
        // Fallback: fully serial on stream 0.
        k_gemm1<<<ggb, 256>>>(x, W1, n);
        k_zero_deg<<<nb, 256>>>(n);
        k_deg<<<eb, 256>>>(ei, e);
        k_scan1<<<nbs, 1024>>>(n);
        k_scan2<<<1, 128>>>(nbs);
        k_scan3<<<nb, 256>>>(n);
        k_fill<<<eb, 256>>>(ei, e);
    }

    k_gather1<<<gnb, 256>>>(b1, n);
    k_gather2_final<<<gnb, 256>>>(W2, b2, (float*)d_out, n);
}

// round 8
// speedup vs baseline: 1.6906x; 1.0028x over previous
#include <cuda_runtime.h>
#include <math.h>

#define NMAX 100000
#define EMAX 3200000
#define FIN  512
#define HID  16
#define NCLS 40

// ---- static scratch (no allocations allowed) ----
__device__ int   g_degi[NMAX];
__device__ int   g_incl[NMAX];
__device__ int   g_bsum[128];
__device__ int   g_rowstart[NMAX];
__device__ int   g_cursor[NMAX];
__device__ int   g_col[EMAX];
__device__ float g_dinv[NMAX];
__device__ __align__(128) float g_h [NMAX * HID];  // raw h = x@W1 (unscaled)
__device__ __align__(128) float g_h2[NMAX * HID];  // hs2 = dinv * relu(agg1+b1)

// packed f32x2 helpers (Blackwell)
#define PACK2(d, lo, hi) \
    asm("mov.b64 %0, {%1, %2};" : "=l"(d) : "f"(lo), "f"(hi))
#define UNPACK2(lo, hi, s) \
    asm("mov.b64 {%0, %1}, %2;" : "=f"(lo), "=f"(hi) : "l"(s))
#define FMA2(d, a, b, c) \
    asm("fma.rn.f32x2 %0, %1, %2, %3;" : "=l"(d) : "l"(a), "l"(b), "l"(c))

// ---------------- degree ----------------
__global__ void k_zero_deg(int n) {
    int i = blockIdx.x * blockDim.x + threadIdx.x;
    if (i < n) g_degi[i] = 0;
}

__global__ void k_deg(const int* __restrict__ ei, int e) {
    int i = blockIdx.x * blockDim.x + threadIdx.x;
    if (i >= e) return;
    atomicAdd(&g_degi[ei[e + i]], 1);   // no return use -> REDG
}

// ---------------- scan1: per-1024-block inclusive scan + block totals + dinv ----------------
__global__ __launch_bounds__(1024) void k_scan1(int n) {
    __shared__ int wsum[32];
    int t = threadIdx.x, lane = t & 31, w = t >> 5;
    int i = blockIdx.x * 1024 + t;
    int dg = (i < n) ? g_degi[i] : 0;
    if (i < n) g_dinv[i] = rsqrtf((float)(dg + 1));   // self-loop adds 1
    int x = dg;
#pragma unroll
    for (int off = 1; off < 32; off <<= 1) {
        int u = __shfl_up_sync(0xffffffffu, x, off);
        if (lane >= off) x += u;
    }
    if (lane == 31) wsum[w] = x;
    __syncthreads();
    if (w == 0) {
        int y = wsum[lane];
#pragma unroll
        for (int off = 1; off < 32; off <<= 1) {
            int u = __shfl_up_sync(0xffffffffu, y, off);
            if (lane >= off) y += u;
        }
        wsum[lane] = y;
    }
    __syncthreads();
    if (w > 0) x += wsum[w - 1];
    if (i < n) g_incl[i] = x;
    if (t == 1023) g_bsum[blockIdx.x] = x;
}

// ---------------- scan3: rowstart/cursor; block offset computed in-kernel ----------------
// 256-thread blocks are aligned inside 1024-element scan1 blocks, so blk is uniform.
__global__ __launch_bounds__(256) void k_scan3(int n) {
    __shared__ int s_off;
    int blk = blockIdx.x >> 2;   // which scan1 block all our elements belong to
    if (threadIdx.x < 32) {
        int s = 0;
        for (int j = threadIdx.x; j < blk; j += 32) s += g_bsum[j];
#pragma unroll
        for (int off = 16; off >= 1; off >>= 1)
            s += __shfl_xor_sync(0xffffffffu, s, off);
        if (threadIdx.x == 0) s_off = s;
    }
    __syncthreads();
    int i = blockIdx.x * 256 + threadIdx.x;
    if (i >= n) return;
    int start = s_off + g_incl[i] - g_degi[i];
    g_rowstart[i] = start;
    g_cursor[i]   = start;
}

// ---------------- CSR fill ----------------
__global__ void k_fill(const int* __restrict__ ei, int e) {
    int i = blockIdx.x * blockDim.x + threadIdx.x;
    if (i >= e) return;
    int s = ei[i];
    int d = ei[e + i];
    int p = atomicAdd(&g_cursor[d], 1);
    g_col[p] = s;
}

// ---------------- GEMM1: h = x @ W1 (raw, packed f32x2) ----------------
#define GROWS 256
#define GKT   32
__global__ __launch_bounds__(256) void k_gemm1(const float* __restrict__ x,
                                               const float* __restrict__ W1, int n) {
    __shared__ __align__(16) float xs[GKT][GROWS + 4];
    __shared__ __align__(16) float ws[GKT][HID];
    int t = threadIdx.x;
    int lane = t & 31, w = t >> 5;
    int rg = t >> 2, cg = t & 3;
    int r0 = blockIdx.x * GROWS;

    unsigned long long acc01[4], acc23[4];
#pragma unroll
    for (int j = 0; j < 4; j++) { acc01[j] = 0ull; acc23[j] = 0ull; }

    for (int kt = 0; kt < FIN; kt += GKT) {
        for (int idx = t; idx < GKT * HID; idx += 256) {
            int kk = idx >> 4, cc = idx & 15;
            ws[kk][cc] = W1[(kt + kk) * HID + cc];
        }
#pragma unroll 4
        for (int i = 0; i < GROWS / 8; i++) {
            int row = i * 8 + w;
            int gr = r0 + row;
            float v = 0.0f;
            if (gr < n) v = x[(long)gr * FIN + kt + lane];
            xs[lane][row] = v;
        }
        __syncthreads();
#pragma unroll
        for (int k = 0; k < GKT; k++) {
            float4 xv = *(const float4*)&xs[k][rg * 4];
            float4 wv = *(const float4*)&ws[k][cg * 4];
            unsigned long long px01, px23, pw0, pw1, pw2, pw3;
            PACK2(px01, xv.x, xv.y);
            PACK2(px23, xv.z, xv.w);
            PACK2(pw0, wv.x, wv.x);
            PACK2(pw1, wv.y, wv.y);
            PACK2(pw2, wv.z, wv.z);
            PACK2(pw3, wv.w, wv.w);
            FMA2(acc01[0], px01, pw0, acc01[0]);
            FMA2(acc23[0], px23, pw0, acc23[0]);
            FMA2(acc01[1], px01, pw1, acc01[1]);
            FMA2(acc23[1], px23, pw1, acc23[1]);
            FMA2(acc01[2], px01, pw2, acc01[2]);
            FMA2(acc23[2], px23, pw2, acc23[2]);
            FMA2(acc01[3], px01, pw3, acc01[3]);
            FMA2(acc23[3], px23, pw3, acc23[3]);
        }
        __syncthreads();
    }

    float acc[4][4];
#pragma unroll
    for (int j = 0; j < 4; j++) {
        UNPACK2(acc[0][j], acc[1][j], acc01[j]);
        UNPACK2(acc[2][j], acc[3][j], acc23[j]);
    }
#pragma unroll
    for (int i = 0; i < 4; i++) {
        int gr = r0 + rg * 4 + i;
        if (gr < n) {
            float4 o = make_float4(acc[i][0], acc[i][1], acc[i][2], acc[i][3]);
            *(float4*)&g_h[gr * HID + cg * 4] = o;
        }
    }
}

// ---------------- gather 1: hs2 = dv * relu(dv*Σ dinv_s h_s + dv^2 h_v + b1) ----------------
// lane layout: slot = lane>>2 (8 neighbor slots), fq = lane&3 (4 float4 feature lanes)
__global__ __launch_bounds__(256) void k_gather1(const float* __restrict__ b1, int n) {
    int v = blockIdx.x * 8 + (threadIdx.x >> 5);
    if (v >= n) return;
    int lane = threadIdx.x & 31;
    int slot = lane >> 2, fq = lane & 3;

    int beg = g_rowstart[v];
    int dg  = g_degi[v];

    float4 acc = make_float4(0.f, 0.f, 0.f, 0.f);
    int j = slot;
    for (; j + 8 < dg; j += 16) {
        int s0 = __ldg(&g_col[beg + j]);
        int s1 = __ldg(&g_col[beg + j + 8]);
        float w0 = __ldg(&g_dinv[s0]);
        float w1 = __ldg(&g_dinv[s1]);
        float4 h0 = *(const float4*)&g_h[s0 * HID + fq * 4];
        float4 h1 = *(const float4*)&g_h[s1 * HID + fq * 4];
        acc.x += w0 * h0.x + w1 * h1.x;
        acc.y += w0 * h0.y + w1 * h1.y;
        acc.z += w0 * h0.z + w1 * h1.z;
        acc.w += w0 * h0.w + w1 * h1.w;
    }
    if (j < dg) {
        int s = __ldg(&g_col[beg + j]);
        float w0 = __ldg(&g_dinv[s]);
        float4 h0 = *(const float4*)&g_h[s * HID + fq * 4];
        acc.x += w0 * h0.x; acc.y += w0 * h0.y;
        acc.z += w0 * h0.z; acc.w += w0 * h0.w;
    }
#pragma unroll
    for (int off = 4; off <= 16; off <<= 1) {
        acc.x += __shfl_xor_sync(0xffffffffu, acc.x, off);
        acc.y += __shfl_xor_sync(0xffffffffu, acc.y, off);
        acc.z += __shfl_xor_sync(0xffffffffu, acc.z, off);
        acc.w += __shfl_xor_sync(0xffffffffu, acc.w, off);
    }

    float dv  = g_dinv[v];
    float dv2 = dv * dv;
    float4 self = *(const float4*)&g_h[v * HID + fq * 4];
    float4 bb   = *(const float4*)&b1[fq * 4];
    float4 o;
    o.x = dv * fmaxf(dv * acc.x + dv2 * self.x + bb.x, 0.0f);
    o.y = dv * fmaxf(dv * acc.y + dv2 * self.y + bb.y, 0.0f);
    o.z = dv * fmaxf(dv * acc.z + dv2 * self.z + bb.z, 0.0f);
    o.w = dv * fmaxf(dv * acc.w + dv2 * self.w + bb.w, 0.0f);
    if (lane < 4) *(float4*)&g_h2[v * HID + fq * 4] = o;
}

// ---------------- gather 2 + W2 + log_softmax ----------------
__global__ __launch_bounds__(256) void k_gather2_final(const float* __restrict__ W2,
                                                       const float* __restrict__ b2,
                                                       float* __restrict__ out, int n) {
    __shared__ float w2s[HID * NCLS];
    __shared__ float b2s[NCLS];
    int t = threadIdx.x;
    for (int idx = t; idx < HID * NCLS; idx += 256) w2s[idx] = W2[idx];
    if (t < NCLS) b2s[t] = b2[t];
    __syncthreads();

    int v = blockIdx.x * 8 + (t >> 5);
    if (v >= n) return;
    int lane = t & 31;
    int slot = lane >> 2, fq = lane & 3;

    int beg = g_rowstart[v];
    int dg  = g_degi[v];

    float4 acc = make_float4(0.f, 0.f, 0.f, 0.f);
    int j = slot;
    for (; j + 8 < dg; j += 16) {
        int s0 = __ldg(&g_col[beg + j]);
        int s1 = __ldg(&g_col[beg + j + 8]);
        float4 h0 = *(const float4*)&g_h2[s0 * HID + fq * 4];
        float4 h1 = *(const float4*)&g_h2[s1 * HID + fq * 4];
        acc.x += h0.x + h1.x; acc.y += h0.y + h1.y;
        acc.z += h0.z + h1.z; acc.w += h0.w + h1.w;
    }
    if (j < dg) {
        int s = __ldg(&g_col[beg + j]);
        float4 h0 = *(const float4*)&g_h2[s * HID + fq * 4];
        acc.x += h0.x; acc.y += h0.y; acc.z += h0.z; acc.w += h0.w;
    }
#pragma unroll
    for (int off = 4; off <= 16; off <<= 1) {
        acc.x += __shfl_xor_sync(0xffffffffu, acc.x, off);
        acc.y += __shfl_xor_sync(0xffffffffu, acc.y, off);
        acc.z += __shfl_xor_sync(0xffffffffu, acc.z, off);
        acc.w += __shfl_xor_sync(0xffffffffu, acc.w, off);
    }

    float dv = g_dinv[v];
    float4 self = *(const float4*)&g_h2[v * HID + fq * 4];
    float av[4];
    av[0] = dv * (acc.x + self.x);
    av[1] = dv * (acc.y + self.y);
    av[2] = dv * (acc.z + self.z);
    av[3] = dv * (acc.w + self.w);

    float a[HID];
#pragma unroll
    for (int k = 0; k < HID; k++)
        a[k] = __shfl_sync(0xffffffffu, av[k & 3], k >> 2);

    float v1 = b2s[lane];
#pragma unroll
    for (int k = 0; k < HID; k++) v1 += a[k] * w2s[k * NCLS + lane];

    float v2 = __int_as_float(0xff800000);  // -inf
    if (lane < 8) {
        int c2 = 32 + lane;
        v2 = b2s[c2];
#pragma unroll
        for (int k = 0; k < HID; k++) v2 += a[k] * w2s[k * NCLS + c2];
    }

    float m = fmaxf(v1, v2);
#pragma unroll
    for (int off = 16; off >= 1; off >>= 1)
        m = fmaxf(m, __shfl_xor_sync(0xffffffffu, m, off));

    float se = __expf(v1 - m) + ((lane < 8) ? __expf(v2 - m) : 0.0f);
#pragma unroll
    for (int off = 16; off >= 1; off >>= 1)
        se += __shfl_xor_sync(0xffffffffu, se, off);

    float lse = __logf(se);
    out[v * NCLS + lane] = v1 - m - lse;
    if (lane < 8) out[v * NCLS + 32 + lane] = v2 - m - lse;
}

extern "C" void kernel_launch(void* const* d_in, const int* in_sizes, int n_in,
                              void* d_out, int out_size) {
    const float* x  = (const float*)d_in[0];
    const float* W1 = (const float*)d_in[1];
    const float* b1 = (const float*)d_in[2];
    const float* W2 = (const float*)d_in[3];
    const float* b2 = (const float*)d_in[4];
    const int*   ei = (const int*)d_in[5];   // int32: JAX x64 disabled

    int n = in_sizes[0] / FIN;
    int e = in_sizes[5] / 2;
    if (n > NMAX) n = NMAX;
    if (e > EMAX) e = EMAX;

    int nb  = (n + 255) / 256;
    int eb  = (e + 255) / 256;
    int nbs = (n + 1023) / 1024;
    int gnb = (n + 7) / 8;              // warp-per-node grids
    int ggb = (n + GROWS - 1) / GROWS;

    // One-time host-side stream/event setup (first call is outside capture).
    static cudaStream_t s2 = nullptr;
    static cudaEvent_t  evF = nullptr, evJ = nullptr;
    static int          tried = 0;
    if (!tried) {
        tried = 1;
        if (cudaStreamCreateWithFlags(&s2, cudaStreamNonBlocking) != cudaSuccess) s2 = nullptr;
        if (s2) {
            if (cudaEventCreateWithFlags(&evF, cudaEventDisableTiming) != cudaSuccess ||
                cudaEventCreateWithFlags(&evJ, cudaEventDisableTiming) != cudaSuccess) {
                s2 = nullptr;
            }
        }
    }

    if (s2) {
        // Fork: gemm1 runs on s2, overlapping the edge-prep chain on stream 0.
        cudaEventRecord(evF, 0);
        cudaStreamWaitEvent(s2, evF, 0);
        k_gemm1<<<ggb, 256, 0, s2>>>(x, W1, n);
        cudaEventRecord(evJ, s2);

        k_zero_deg<<<nb, 256>>>(n);
        k_deg<<<eb, 256>>>(ei, e);
        k_scan1<<<nbs, 1024>>>(n);
        k_scan3<<<nb, 256>>>(n);
        k_fill<<<eb, 256>>>(ei, e);

        cudaStreamWaitEvent(0, evJ, 0);   // join before gather1
    } else {
        // Fallback: fully serial on stream 0.
        k_gemm1<<<ggb, 256>>>(x, W1, n);
        k_zero_deg<<<nb, 256>>>(n);
        k_deg<<<eb, 256>>>(ei, e);
        k_scan1<<<nbs, 1024>>>(n);
        k_scan3<<<nb, 256>>>(n);
        k_fill<<<eb, 256>>>(ei, e);
    }

    k_gather1<<<gnb, 256>>>(b1, n);
    k_gather2_final<<<gnb, 256>>>(W2, b2, (float*)d_out, n);
}